// round 2
// baseline (speedup 1.0000x reference)
#include <cuda_runtime.h>

// Problem constants
constexpr int Bn = 2048, Tn = 128, OBn = 64, ACn = 8, OBLn = 32, ACLn = 16, Wn = 64;

// Scratch (device globals: allocation-free rule)
__device__ float g_acl[(size_t)Bn * Tn * ACLn];   // (B,T,16) action latents
__device__ float g_y0[(size_t)Bn * OBLn];         // (B,32)   encoded initial latents
__device__ float g_ys[(size_t)Bn * Tn * OBLn];    // (B,T,32) integrated latents

// ---------------------------------------------------------------------------
// Action-latent encoder: (B*T, 8) -> 64 relu -> 16
// ---------------------------------------------------------------------------
__global__ __launch_bounds__(256) void ac_kernel(
    const float* __restrict__ acs, const float* __restrict__ W0,
    const float* __restrict__ b0, const float* __restrict__ W1,
    const float* __restrict__ b1)
{
    __shared__ __align__(16) float sW0[64 * 8];
    __shared__ __align__(16) float sW1[16 * 64];
    __shared__ float sb0[64], sb1[16];
    for (int i = threadIdx.x; i < 512; i += 256) sW0[i] = W0[i];
    for (int i = threadIdx.x; i < 1024; i += 256) sW1[i] = W1[i];
    if (threadIdx.x < 64) sb0[threadIdx.x] = b0[threadIdx.x];
    if (threadIdx.x < 16) sb1[threadIdx.x] = b1[threadIdx.x];
    __syncthreads();

    const int r = blockIdx.x * 256 + threadIdx.x;   // row in [0, B*T)
    const float4* a4 = (const float4*)acs;
    float4 xa = a4[r * 2], xb = a4[r * 2 + 1];
    float x[8] = {xa.x, xa.y, xa.z, xa.w, xb.x, xb.y, xb.z, xb.w};

    float h[64];
#pragma unroll 8
    for (int j = 0; j < 64; j++) {
        float4 wv0 = *(const float4*)(sW0 + j * 8);
        float4 wv1 = *(const float4*)(sW0 + j * 8 + 4);
        float a = sb0[j];
        a = fmaf(wv0.x, x[0], a); a = fmaf(wv0.y, x[1], a);
        a = fmaf(wv0.z, x[2], a); a = fmaf(wv0.w, x[3], a);
        a = fmaf(wv1.x, x[4], a); a = fmaf(wv1.y, x[5], a);
        a = fmaf(wv1.z, x[6], a); a = fmaf(wv1.w, x[7], a);
        h[j] = fmaxf(a, 0.f);
    }

    float4* out4 = (float4*)g_acl;
#pragma unroll
    for (int o = 0; o < 16; o += 4) {
        float a0 = sb1[o], a1 = sb1[o + 1], a2 = sb1[o + 2], a3 = sb1[o + 3];
#pragma unroll
        for (int j = 0; j < 64; j += 4) {
            float4 v0 = *(const float4*)(sW1 + (o + 0) * 64 + j);
            float4 v1 = *(const float4*)(sW1 + (o + 1) * 64 + j);
            float4 v2 = *(const float4*)(sW1 + (o + 2) * 64 + j);
            float4 v3 = *(const float4*)(sW1 + (o + 3) * 64 + j);
            a0 = fmaf(v0.x, h[j], a0); a0 = fmaf(v0.y, h[j+1], a0); a0 = fmaf(v0.z, h[j+2], a0); a0 = fmaf(v0.w, h[j+3], a0);
            a1 = fmaf(v1.x, h[j], a1); a1 = fmaf(v1.y, h[j+1], a1); a1 = fmaf(v1.z, h[j+2], a1); a1 = fmaf(v1.w, h[j+3], a1);
            a2 = fmaf(v2.x, h[j], a2); a2 = fmaf(v2.y, h[j+1], a2); a2 = fmaf(v2.z, h[j+2], a2); a2 = fmaf(v2.w, h[j+3], a2);
            a3 = fmaf(v3.x, h[j], a3); a3 = fmaf(v3.y, h[j+1], a3); a3 = fmaf(v3.z, h[j+2], a3); a3 = fmaf(v3.w, h[j+3], a3);
        }
        out4[r * 4 + o / 4] = make_float4(a0, a1, a2, a3);
    }
}

// ---------------------------------------------------------------------------
// Observation encoder: (B, 64) -> 64 relu -> 32
// ---------------------------------------------------------------------------
__global__ __launch_bounds__(64) void enc_kernel(
    const float* __restrict__ ob, const float* __restrict__ W0,
    const float* __restrict__ b0, const float* __restrict__ W1,
    const float* __restrict__ b1)
{
    __shared__ __align__(16) float sW0[64 * 64];
    __shared__ __align__(16) float sW1[32 * 64];
    __shared__ float sb0[64], sb1[32];
    for (int i = threadIdx.x; i < 4096; i += 64) sW0[i] = W0[i];
    for (int i = threadIdx.x; i < 2048; i += 64) sW1[i] = W1[i];
    if (threadIdx.x < 64) sb0[threadIdx.x] = b0[threadIdx.x];
    if (threadIdx.x < 32) sb1[threadIdx.x] = b1[threadIdx.x];
    __syncthreads();

    const int r = blockIdx.x * 64 + threadIdx.x;   // row in [0, B)
    float x[64];
#pragma unroll
    for (int c = 0; c < 64; c += 4) {
        float4 v = *(const float4*)(ob + r * 64 + c);
        x[c] = v.x; x[c+1] = v.y; x[c+2] = v.z; x[c+3] = v.w;
    }
    float h[64];
#pragma unroll 4
    for (int j = 0; j < 64; j++) {
        float a = sb0[j];
#pragma unroll
        for (int c = 0; c < 64; c += 4) {
            float4 w = *(const float4*)(sW0 + j * 64 + c);
            a = fmaf(w.x, x[c], a); a = fmaf(w.y, x[c+1], a);
            a = fmaf(w.z, x[c+2], a); a = fmaf(w.w, x[c+3], a);
        }
        h[j] = fmaxf(a, 0.f);
    }
#pragma unroll 1
    for (int o = 0; o < 32; o += 4) {
        float a0 = sb1[o], a1 = sb1[o+1], a2 = sb1[o+2], a3 = sb1[o+3];
#pragma unroll
        for (int j = 0; j < 64; j += 4) {
            float4 v0 = *(const float4*)(sW1 + (o + 0) * 64 + j);
            float4 v1 = *(const float4*)(sW1 + (o + 1) * 64 + j);
            float4 v2 = *(const float4*)(sW1 + (o + 2) * 64 + j);
            float4 v3 = *(const float4*)(sW1 + (o + 3) * 64 + j);
            a0 = fmaf(v0.x, h[j], a0); a0 = fmaf(v0.y, h[j+1], a0); a0 = fmaf(v0.z, h[j+2], a0); a0 = fmaf(v0.w, h[j+3], a0);
            a1 = fmaf(v1.x, h[j], a1); a1 = fmaf(v1.y, h[j+1], a1); a1 = fmaf(v1.z, h[j+2], a1); a1 = fmaf(v1.w, h[j+3], a1);
            a2 = fmaf(v2.x, h[j], a2); a2 = fmaf(v2.y, h[j+1], a2); a2 = fmaf(v2.z, h[j+2], a2); a2 = fmaf(v2.w, h[j+3], a2);
            a3 = fmaf(v3.x, h[j], a3); a3 = fmaf(v3.y, h[j+1], a3); a3 = fmaf(v3.z, h[j+2], a3); a3 = fmaf(v3.w, h[j+3], a3);
        }
        *(float4*)(g_y0 + r * 32 + o) = make_float4(a0, a1, a2, a3);
    }
}

// ---------------------------------------------------------------------------
// Dynamics MLP stage: x(48)=concat(y,acl) -> 64 relu -> 32, one warp, one elem
// Lane l: computes h[l], h[l+32] (weights in regs), returns out[l].
// ---------------------------------------------------------------------------
__device__ __forceinline__ float dyn_eval(
    float xl, int lane, float* __restrict__ xw, float* __restrict__ hw,
    const float* __restrict__ w0a, const float* __restrict__ w0b,
    const float* __restrict__ w1r, float b0a, float b0b, float b1l)
{
    xw[lane] = xl;
    __syncwarp();
    float h0 = b0a, h1 = b0b;
#pragma unroll
    for (int c = 0; c < 48; c += 4) {
        float4 xv = *(const float4*)(xw + c);
        h0 = fmaf(w0a[c],   xv.x, h0); h1 = fmaf(w0b[c],   xv.x, h1);
        h0 = fmaf(w0a[c+1], xv.y, h0); h1 = fmaf(w0b[c+1], xv.y, h1);
        h0 = fmaf(w0a[c+2], xv.z, h0); h1 = fmaf(w0b[c+2], xv.z, h1);
        h0 = fmaf(w0a[c+3], xv.w, h0); h1 = fmaf(w0b[c+3], xv.w, h1);
    }
    hw[lane]      = fmaxf(h0, 0.f);
    hw[lane + 32] = fmaxf(h1, 0.f);
    __syncwarp();
    float o = b1l;
#pragma unroll
    for (int j = 0; j < 64; j += 4) {
        float4 hv = *(const float4*)(hw + j);
        o = fmaf(w1r[j],   hv.x, o);
        o = fmaf(w1r[j+1], hv.y, o);
        o = fmaf(w1r[j+2], hv.z, o);
        o = fmaf(w1r[j+3], hv.w, o);
    }
    return o;
}

// ---------------------------------------------------------------------------
// Main ODE integration: one warp per batch element, 2 elements per warp.
// ---------------------------------------------------------------------------
__global__ __launch_bounds__(64) void ode_kernel(
    const float* __restrict__ timesg,
    const float* __restrict__ dW0, const float* __restrict__ db0,
    const float* __restrict__ dW1, const float* __restrict__ db1)
{
    __shared__ __align__(16) float sx[2][48];
    __shared__ __align__(16) float sh[2][64];
    const int w    = threadIdx.x >> 5;
    const int lane = threadIdx.x & 31;
    float* xw = sx[w];
    float* hw = sh[w];
    const int wg = blockIdx.x * 2 + w;

    // Per-lane weight registers: dynW0 rows lane, lane+32; dynW1 row lane.
    float w0a[48], w0b[48], w1r[64];
#pragma unroll
    for (int c = 0; c < 48; c += 4) {
        float4 v = *(const float4*)(dW0 + lane * 48 + c);
        w0a[c] = v.x; w0a[c+1] = v.y; w0a[c+2] = v.z; w0a[c+3] = v.w;
        float4 u = *(const float4*)(dW0 + (lane + 32) * 48 + c);
        w0b[c] = u.x; w0b[c+1] = u.y; w0b[c+2] = u.z; w0b[c+3] = u.w;
    }
#pragma unroll
    for (int j = 0; j < 64; j += 4) {
        float4 v = *(const float4*)(dW1 + lane * 64 + j);
        w1r[j] = v.x; w1r[j+1] = v.y; w1r[j+2] = v.z; w1r[j+3] = v.w;
    }
    const float b0a = db0[lane], b0b = db0[lane + 32], b1l = db1[lane];

    for (int e = 0; e < 2; e++) {
        const int bidx = wg * 2 + e;
        const float* tb = timesg + bidx * Tn;
        const float* ab = g_acl + (size_t)bidx * Tn * ACLn;
        float* yout = g_ys + (size_t)bidx * Tn * OBLn;

        float y = g_y0[bidx * OBLn + lane];
        yout[lane] = y;
        int cur = -1;

#pragma unroll 1
        for (int i = 0; i < Tn - 1; i++) {
            const float t0 = tb[i], t1 = tb[i + 1];
            const float h = (t1 - t0) * 0.5f;     // == (t1-t0)/K, K=2
            if (cur != i) {
                if (lane < ACLn) xw[32 + lane] = ab[i * ACLn + lane];
                cur = i;
            }
#pragma unroll 1
            for (int j = 0; j < 2; j++) {
                const float t = t0 + (float)j * h;   // matches JAX fp32 exactly

                float k1 = dyn_eval(y, lane, xw, hw, w0a, w0b, w1r, b0a, b0b, b1l);
                float k2 = dyn_eval(fmaf(h, 0.2f * k1, y), lane, xw, hw, w0a, w0b, w1r, b0a, b0b, b1l);
                float acc = 0.075f * k1;
                acc = fmaf(0.225f, k2, acc);
                float k3 = dyn_eval(fmaf(h, acc, y), lane, xw, hw, w0a, w0b, w1r, b0a, b0b, b1l);
                acc = (44.f / 45.f) * k1;
                acc = fmaf(-(56.f / 15.f), k2, acc);
                acc = fmaf(32.f / 9.f, k3, acc);
                float k4 = dyn_eval(fmaf(h, acc, y), lane, xw, hw, w0a, w0b, w1r, b0a, b0b, b1l);
                acc = (19372.f / 6561.f) * k1;
                acc = fmaf(-(25360.f / 2187.f), k2, acc);
                acc = fmaf(64448.f / 6561.f, k3, acc);
                acc = fmaf(-(212.f / 729.f), k4, acc);
                float k5 = dyn_eval(fmaf(h, acc, y), lane, xw, hw, w0a, w0b, w1r, b0a, b0b, b1l);

                // stage-6 time t+h can reach t1 -> piecewise-constant action switches
                // (searchsorted side='right' semantics: idx advances iff ts >= t1)
                const float ts6 = t + h;
                const int want = (ts6 >= t1) ? (i + 1) : i;   // i+1 <= T-1 always
                if (want != cur) {
                    if (lane < ACLn) xw[32 + lane] = ab[want * ACLn + lane];
                    cur = want;
                }
                acc = (9017.f / 3168.f) * k1;
                acc = fmaf(-(355.f / 33.f), k2, acc);
                acc = fmaf(46732.f / 5247.f, k3, acc);
                acc = fmaf(49.f / 176.f, k4, acc);
                acc = fmaf(-(5103.f / 18656.f), k5, acc);
                float k6 = dyn_eval(fmaf(h, acc, y), lane, xw, hw, w0a, w0b, w1r, b0a, b0b, b1l);

                acc = (35.f / 384.f) * k1;
                acc = fmaf(500.f / 1113.f, k3, acc);
                acc = fmaf(125.f / 192.f, k4, acc);
                acc = fmaf(-(2187.f / 6784.f), k5, acc);
                acc = fmaf(11.f / 84.f, k6, acc);
                y = fmaf(h, acc, y);
            }
            yout[(i + 1) * OBLn + lane] = y;
        }
    }
}

// ---------------------------------------------------------------------------
// Decoder: (B*T, 32) -> 64 relu -> 64
// ---------------------------------------------------------------------------
__global__ __launch_bounds__(256) void dec_kernel(
    const float* __restrict__ W0, const float* __restrict__ b0,
    const float* __restrict__ W1, const float* __restrict__ b1,
    float* __restrict__ out)
{
    __shared__ __align__(16) float sW0[64 * 32];
    __shared__ __align__(16) float sW1[64 * 64];
    __shared__ float sb0[64], sb1[64];
    for (int i = threadIdx.x; i < 2048; i += 256) sW0[i] = W0[i];
    for (int i = threadIdx.x; i < 4096; i += 256) sW1[i] = W1[i];
    if (threadIdx.x < 64) { sb0[threadIdx.x] = b0[threadIdx.x]; sb1[threadIdx.x] = b1[threadIdx.x]; }
    __syncthreads();

    const int r = blockIdx.x * 256 + threadIdx.x;   // row in [0, B*T)
    float x[32];
#pragma unroll
    for (int c = 0; c < 32; c += 4) {
        float4 v = *(const float4*)(g_ys + (size_t)r * 32 + c);
        x[c] = v.x; x[c+1] = v.y; x[c+2] = v.z; x[c+3] = v.w;
    }
    float h[64];
#pragma unroll 4
    for (int j = 0; j < 64; j++) {
        float a = sb0[j];
#pragma unroll
        for (int c = 0; c < 32; c += 4) {
            float4 wv = *(const float4*)(sW0 + j * 32 + c);
            a = fmaf(wv.x, x[c], a); a = fmaf(wv.y, x[c+1], a);
            a = fmaf(wv.z, x[c+2], a); a = fmaf(wv.w, x[c+3], a);
        }
        h[j] = fmaxf(a, 0.f);
    }
#pragma unroll 1
    for (int o = 0; o < 64; o += 4) {
        float a0 = sb1[o], a1 = sb1[o+1], a2 = sb1[o+2], a3 = sb1[o+3];
#pragma unroll
        for (int j = 0; j < 64; j += 4) {
            float4 v0 = *(const float4*)(sW1 + (o + 0) * 64 + j);
            float4 v1 = *(const float4*)(sW1 + (o + 1) * 64 + j);
            float4 v2 = *(const float4*)(sW1 + (o + 2) * 64 + j);
            float4 v3 = *(const float4*)(sW1 + (o + 3) * 64 + j);
            a0 = fmaf(v0.x, h[j], a0); a0 = fmaf(v0.y, h[j+1], a0); a0 = fmaf(v0.z, h[j+2], a0); a0 = fmaf(v0.w, h[j+3], a0);
            a1 = fmaf(v1.x, h[j], a1); a1 = fmaf(v1.y, h[j+1], a1); a1 = fmaf(v1.z, h[j+2], a1); a1 = fmaf(v1.w, h[j+3], a1);
            a2 = fmaf(v2.x, h[j], a2); a2 = fmaf(v2.y, h[j+1], a2); a2 = fmaf(v2.z, h[j+2], a2); a2 = fmaf(v2.w, h[j+3], a2);
            a3 = fmaf(v3.x, h[j], a3); a3 = fmaf(v3.y, h[j+1], a3); a3 = fmaf(v3.z, h[j+2], a3); a3 = fmaf(v3.w, h[j+3], a3);
        }
        *(float4*)(out + (size_t)r * 64 + o) = make_float4(a0, a1, a2, a3);
    }
}

// ---------------------------------------------------------------------------
extern "C" void kernel_launch(void* const* d_in, const int* in_sizes, int n_in,
                              void* d_out, int out_size)
{
    const float* encW0 = (const float*)d_in[0];
    const float* encb0 = (const float*)d_in[1];
    const float* encW1 = (const float*)d_in[2];
    const float* encb1 = (const float*)d_in[3];
    const float* acW0  = (const float*)d_in[4];
    const float* acb0  = (const float*)d_in[5];
    const float* acW1  = (const float*)d_in[6];
    const float* acb1  = (const float*)d_in[7];
    const float* dynW0 = (const float*)d_in[8];
    const float* dynb0 = (const float*)d_in[9];
    const float* dynW1 = (const float*)d_in[10];
    const float* dynb1 = (const float*)d_in[11];
    const float* decW0 = (const float*)d_in[12];
    const float* decb0 = (const float*)d_in[13];
    const float* decW1 = (const float*)d_in[14];
    const float* decb1 = (const float*)d_in[15];
    const float* ob    = (const float*)d_in[16];
    const float* acs   = (const float*)d_in[17];
    const float* times = (const float*)d_in[18];

    ac_kernel<<<(Bn * Tn) / 256, 256>>>(acs, acW0, acb0, acW1, acb1);
    enc_kernel<<<Bn / 64, 64>>>(ob, encW0, encb0, encW1, encb1);
    ode_kernel<<<Bn / 4, 64>>>(times, dynW0, dynb0, dynW1, dynb1);
    dec_kernel<<<(Bn * Tn) / 256, 256>>>(decW0, decb0, decW1, decb1, (float*)d_out);
}